// round 13
// baseline (speedup 1.0000x reference)
#include <cuda_runtime.h>
#include <cuda_fp16.h>
#include <mma.h>
using namespace nvcuda;

#define HD 128
#define MAXN 100096
#define MAXE 1600000
#define SK 136   // smem stride in halves (padded)
#define CAP 128  // fixed CSR bucket capacity per node (max degree ~45 for this data)

// ---------------- device scratch (static, no allocation) ----------------
__device__ __align__(16) __half g_bufH[MAXN * HD];  // GEMM output (fp16, gathered by agg)
__device__ __align__(16) __half g_bufB[MAXN * HD];  // aggregation output (fp16 activations)
__device__ int g_cnt[MAXN];          // per-dst degree (atomic)
__device__ int g_csr[MAXN * CAP];    // fixed-stride buckets of src indices

// ---------------- single-pass CSR build ----------------
__global__ void build_csr_kernel(const int* __restrict__ adj, int E_) {
    int e = blockIdx.x * blockDim.x + threadIdx.x;
    if (e < E_) {
        int s = adj[e];
        int d = adj[E_ + e];
        int slot = atomicAdd(&g_cnt[d], 1);
        if (slot < CAP) g_csr[d * CAP + slot] = s;
    }
}

// ---------------- tensor-core GEMM (R6/R10 version, verbatim) ----------------
// C[r] = fp16( (A[r] @ W + b) * norm[r] ),  norm[r] = rsqrt(cnt[r]) (0 if cnt==0)
// 256 threads, 128-row tile, K=128 resident, HMMA fp16-in/fp32-accum.
template<bool AHALF>
__global__ void gemm_mma_kernel(const void* __restrict__ Ain,
                                const float* __restrict__ W,
                                const float* __restrict__ bias,
                                __half* __restrict__ C, int n) {
    extern __shared__ char smem_raw[];
    __half* As = (__half*)smem_raw;           // 128 x SK halves
    __half* Ws = As + 128 * SK;               // 128 x SK halves
    float* stage = (float*)smem_raw;          // reused after mma loop
    int tid = threadIdx.x;
    int row0 = blockIdx.x * 128;

    // W fp32 -> fp16 smem
    {
        const float4* W4 = (const float4*)W;
        #pragma unroll
        for (int i = tid; i < 128 * 32; i += 256) {
            int r = i >> 5, c4 = i & 31;
            float4 v = W4[i];
            __half2* d = (__half2*)(Ws + r * SK + c4 * 4);
            d[0] = __floats2half2_rn(v.x, v.y);
            d[1] = __floats2half2_rn(v.z, v.w);
        }
    }
    // A tile -> fp16 smem
    if (AHALF) {
        const uint4* A4 = (const uint4*)Ain;   // 8 halves per uint4, 16 per row
        #pragma unroll
        for (int i = tid; i < 128 * 16; i += 256) {
            int r = i >> 4, c8 = i & 15;
            int gr = row0 + r;
            uint4 v = (gr < n) ? A4[gr * 16 + c8] : make_uint4(0, 0, 0, 0);
            *(uint4*)(As + r * SK + c8 * 8) = v;
        }
    } else {
        const float4* A4 = (const float4*)Ain;
        #pragma unroll
        for (int i = tid; i < 128 * 32; i += 256) {
            int r = i >> 5, c4 = i & 31;
            int gr = row0 + r;
            float4 v = (gr < n) ? A4[gr * 32 + c4] : make_float4(0.f, 0.f, 0.f, 0.f);
            __half2* d = (__half2*)(As + r * SK + c4 * 4);
            d[0] = __floats2half2_rn(v.x, v.y);
            d[1] = __floats2half2_rn(v.z, v.w);
        }
    }
    __syncthreads();

    int w = tid >> 5;
    int lane = tid & 31;
    int wm = (w >> 1) * 32;     // warp row base
    int wn = (w & 1) * 64;      // warp col base

    wmma::fragment<wmma::accumulator, 16, 16, 16, float> acc[2][4];
    #pragma unroll
    for (int p = 0; p < 2; p++)
        #pragma unroll
        for (int q = 0; q < 4; q++) wmma::fill_fragment(acc[p][q], 0.0f);

    #pragma unroll
    for (int k = 0; k < 128; k += 16) {
        wmma::fragment<wmma::matrix_a, 16, 16, 16, __half, wmma::row_major> af[2];
        wmma::fragment<wmma::matrix_b, 16, 16, 16, __half, wmma::row_major> bf[4];
        #pragma unroll
        for (int p = 0; p < 2; p++)
            wmma::load_matrix_sync(af[p], As + (wm + 16 * p) * SK + k, SK);
        #pragma unroll
        for (int q = 0; q < 4; q++)
            wmma::load_matrix_sync(bf[q], Ws + k * SK + wn + 16 * q, SK);
        #pragma unroll
        for (int p = 0; p < 2; p++)
            #pragma unroll
            for (int q = 0; q < 4; q++)
                wmma::mma_sync(acc[p][q], af[p], bf[q], acc[p][q]);
    }
    __syncthreads();   // all warps done reading As/Ws before staging overwrites

    float* st = stage + w * (32 * 72);
    #pragma unroll
    for (int p = 0; p < 2; p++)
        #pragma unroll
        for (int q = 0; q < 4; q++)
            wmma::store_matrix_sync(st + 16 * p * 72 + 16 * q, acc[p][q], 72,
                                    wmma::mem_row_major);
    __syncwarp();

    // epilogue: (v + bias) * norm[row] -> fp16
    float2 bb = ((const float2*)bias)[(wn >> 1) + lane];
    __half2* C2 = (__half2*)C;
    #pragma unroll
    for (int r = 0; r < 32; r++) {
        int gr = row0 + wm + r;
        if (gr < n) {
            int c = g_cnt[gr];
            float nr = (c > 0) ? rsqrtf((float)c) : 0.0f;
            float2 v = *(float2*)(st + r * 72 + lane * 2);
            C2[gr * 64 + (wn >> 1) + lane] =
                __floats2half2_rn((v.x + bb.x) * nr, (v.y + bb.y) * nr);
        }
    }
}

// ---- aggregation: Out[d] = fp16( relu(norm[d] * sum_{src in bucket(d)} Hs[src]) ) ----
// one warp per dst node; lane l owns 4 halves (8B) of the 256B fp16 row.
// OCT inner step: 8 independent LDGs in flight, three-level fp16 pairwise tree,
// one convert per 8 edges; fp32 accumulation above.
__global__ void aggregate_kernel(const __half* __restrict__ Hs,
                                 __half* __restrict__ Out, int n) {
    int gw = (blockIdx.x * blockDim.x + threadIdx.x) >> 5;
    int lane = threadIdx.x & 31;
    if (gw >= n) return;
    int cnt_true = g_cnt[gw];
    int cnt = cnt_true < CAP ? cnt_true : CAP;
    const int* bucket = g_csr + gw * CAP;
    const uint2* H2 = (const uint2*)Hs;   // row stride = 32 uint2 (256B)
    float ax = 0.f, ay = 0.f, az = 0.f, aw = 0.f;
    for (int base = 0; base < cnt; base += 32) {
        int rem = cnt - base;
        int e = 0;
        if (lane < rem) e = bucket[base + lane];
        int m = rem < 32 ? rem : 32;
        int j = 0;
        for (; j + 8 <= m; j += 8) {
            int s0 = __shfl_sync(0xffffffffu, e, j);
            int s1 = __shfl_sync(0xffffffffu, e, j + 1);
            int s2 = __shfl_sync(0xffffffffu, e, j + 2);
            int s3 = __shfl_sync(0xffffffffu, e, j + 3);
            int s4 = __shfl_sync(0xffffffffu, e, j + 4);
            int s5 = __shfl_sync(0xffffffffu, e, j + 5);
            int s6 = __shfl_sync(0xffffffffu, e, j + 6);
            int s7 = __shfl_sync(0xffffffffu, e, j + 7);
            uint2 v0 = __ldg(&H2[s0 * 32 + lane]);
            uint2 v1 = __ldg(&H2[s1 * 32 + lane]);
            uint2 v2 = __ldg(&H2[s2 * 32 + lane]);
            uint2 v3 = __ldg(&H2[s3 * 32 + lane]);
            uint2 v4 = __ldg(&H2[s4 * 32 + lane]);
            uint2 v5 = __ldg(&H2[s5 * 32 + lane]);
            uint2 v6 = __ldg(&H2[s6 * 32 + lane]);
            uint2 v7 = __ldg(&H2[s7 * 32 + lane]);
            __half2 a01 = __hadd2(*(__half2*)&v0.x, *(__half2*)&v1.x);
            __half2 b01 = __hadd2(*(__half2*)&v0.y, *(__half2*)&v1.y);
            __half2 a23 = __hadd2(*(__half2*)&v2.x, *(__half2*)&v3.x);
            __half2 b23 = __hadd2(*(__half2*)&v2.y, *(__half2*)&v3.y);
            __half2 a45 = __hadd2(*(__half2*)&v4.x, *(__half2*)&v5.x);
            __half2 b45 = __hadd2(*(__half2*)&v4.y, *(__half2*)&v5.y);
            __half2 a67 = __hadd2(*(__half2*)&v6.x, *(__half2*)&v7.x);
            __half2 b67 = __hadd2(*(__half2*)&v6.y, *(__half2*)&v7.y);
            __half2 a03 = __hadd2(a01, a23);
            __half2 b03 = __hadd2(b01, b23);
            __half2 a47 = __hadd2(a45, a67);
            __half2 b47 = __hadd2(b45, b67);
            __half2 r0 = __hadd2(a03, a47);
            __half2 r1 = __hadd2(b03, b47);
            float2 f0 = __half22float2(r0);
            float2 f1 = __half22float2(r1);
            ax += f0.x; ay += f0.y; az += f1.x; aw += f1.y;
        }
        if (j + 4 <= m) {
            int s0 = __shfl_sync(0xffffffffu, e, j);
            int s1 = __shfl_sync(0xffffffffu, e, j + 1);
            int s2 = __shfl_sync(0xffffffffu, e, j + 2);
            int s3 = __shfl_sync(0xffffffffu, e, j + 3);
            uint2 v0 = __ldg(&H2[s0 * 32 + lane]);
            uint2 v1 = __ldg(&H2[s1 * 32 + lane]);
            uint2 v2 = __ldg(&H2[s2 * 32 + lane]);
            uint2 v3 = __ldg(&H2[s3 * 32 + lane]);
            __half2 p0 = __hadd2(*(__half2*)&v0.x, *(__half2*)&v1.x);
            __half2 p1 = __hadd2(*(__half2*)&v0.y, *(__half2*)&v1.y);
            __half2 q0 = __hadd2(*(__half2*)&v2.x, *(__half2*)&v3.x);
            __half2 q1 = __hadd2(*(__half2*)&v2.y, *(__half2*)&v3.y);
            __half2 r0 = __hadd2(p0, q0);
            __half2 r1 = __hadd2(p1, q1);
            float2 f0 = __half22float2(r0);
            float2 f1 = __half22float2(r1);
            ax += f0.x; ay += f0.y; az += f1.x; aw += f1.y;
            j += 4;
        }
        if (j + 2 <= m) {
            int s0 = __shfl_sync(0xffffffffu, e, j);
            int s1 = __shfl_sync(0xffffffffu, e, j + 1);
            uint2 v0 = __ldg(&H2[s0 * 32 + lane]);
            uint2 v1 = __ldg(&H2[s1 * 32 + lane]);
            __half2 p0 = __hadd2(*(__half2*)&v0.x, *(__half2*)&v1.x);
            __half2 p1 = __hadd2(*(__half2*)&v0.y, *(__half2*)&v1.y);
            float2 f0 = __half22float2(p0);
            float2 f1 = __half22float2(p1);
            ax += f0.x; ay += f0.y; az += f1.x; aw += f1.y;
            j += 2;
        }
        if (j < m) {
            int s = __shfl_sync(0xffffffffu, e, j);
            uint2 v = __ldg(&H2[s * 32 + lane]);
            float2 f0 = __half22float2(*(__half2*)&v.x);
            float2 f1 = __half22float2(*(__half2*)&v.y);
            ax += f0.x; ay += f0.y; az += f1.x; aw += f1.y;
        }
    }
    float nr = (cnt_true > 0) ? rsqrtf((float)cnt_true) : 0.0f;
    __half2 o0 = __floats2half2_rn(fmaxf(ax * nr, 0.f), fmaxf(ay * nr, 0.f));
    __half2 o1 = __floats2half2_rn(fmaxf(az * nr, 0.f), fmaxf(aw * nr, 0.f));
    uint2 o;
    o.x = *(unsigned*)&o0;
    o.y = *(unsigned*)&o1;
    ((uint2*)Out)[gw * 32 + lane] = o;
}

// ---------------- pooling + MLP head (one block per graph) ----------------
__device__ __forceinline__ int lower_bound_dev(const int* a, int n, int key) {
    int lo = 0, hi = n;
    while (lo < hi) {
        int mid = (lo + hi) >> 1;
        if (a[mid] < key) lo = mid + 1; else hi = mid;
    }
    return lo;
}

__global__ void pool_head_kernel(const __half* __restrict__ H,
                                 const int* __restrict__ gidx,
                                 const float* __restrict__ Wfc,
                                 const float* __restrict__ bfc,
                                 const float* __restrict__ Wout,
                                 const float* __restrict__ bout,
                                 float* __restrict__ out, int n) {
    __shared__ float gf[HD];
    __shared__ float red[HD];
    __shared__ int bounds[2];
    int g = blockIdx.x, t = threadIdx.x;
    if (t < 2) bounds[t] = lower_bound_dev(gidx, n, g + t);
    __syncthreads();
    int start = bounds[0], end = bounds[1];
    float s = 0.f;
    for (int i = start; i < end; i++) s += __half2float(H[i * HD + t]);
    gf[t] = s / fmaxf((float)(end - start), 1.0f);
    __syncthreads();
    float acc = bfc[t];
    #pragma unroll 8
    for (int k = 0; k < HD; k++) acc += gf[k] * Wfc[k * HD + t];
    red[t] = fmaxf(acc, 0.f) * Wout[t];
    __syncthreads();
    #pragma unroll
    for (int sft = 64; sft > 0; sft >>= 1) {
        if (t < sft) red[t] += red[t + sft];
        __syncthreads();
    }
    if (t == 0) out[g] = red[0] + bout[0];
}

// ---------------- launch ----------------
extern "C" void kernel_launch(void* const* d_in, const int* in_sizes, int n_in,
                              void* d_out, int out_size) {
    const float* node = (const float*)d_in[0];
    const int*   adj  = (const int*)d_in[1];
    const int*   gidx = (const int*)d_in[2];
    // d_in[3] = is_training (ignored, eval mode)
    const float* W1   = (const float*)d_in[4];
    const float* b1   = (const float*)d_in[5];
    const float* W2   = (const float*)d_in[6];
    const float* b2   = (const float*)d_in[7];
    const float* Wfc  = (const float*)d_in[8];
    const float* bfc  = (const float*)d_in[9];
    const float* Wout = (const float*)d_in[10];
    const float* bout = (const float*)d_in[11];

    int n  = in_sizes[2];          // N nodes
    int E_ = in_sizes[1] / 2;      // E edges
    int G_ = out_size;             // G graphs (OUT=1)

    __half* bufH; __half* bufB; int* cntPtr;
    cudaGetSymbolAddress((void**)&bufH, g_bufH);
    cudaGetSymbolAddress((void**)&bufB, g_bufB);
    cudaGetSymbolAddress((void**)&cntPtr, g_cnt);

    // smem: max(two 128xSK half tiles, 8 warps * 32*72 floats staging)
    const int gemm_smem = (2 * 128 * SK * 2 > 8 * 32 * 72 * 4)
                              ? 2 * 128 * SK * 2 : 8 * 32 * 72 * 4;
    cudaFuncSetAttribute(gemm_mma_kernel<false>,
                         cudaFuncAttributeMaxDynamicSharedMemorySize, gemm_smem);
    cudaFuncSetAttribute(gemm_mma_kernel<true>,
                         cudaFuncAttributeMaxDynamicSharedMemorySize, gemm_smem);

    int gemm_blocks = (n + 127) / 128;
    int agg_blocks  = (n + 7) / 8;   // 8 warps / block, 1 warp per node

    // single-pass CSR build (degrees + fixed-stride buckets)
    cudaMemsetAsync(cntPtr, 0, (size_t)MAXN * sizeof(int));
    build_csr_kernel<<<(E_ + 255) / 256, 256>>>(adj, E_);

    // layer 1
    gemm_mma_kernel<false><<<gemm_blocks, 256, gemm_smem>>>(node, W1, b1, bufH, n);
    aggregate_kernel<<<agg_blocks, 256>>>(bufH, bufB, n);
    // layer 2
    gemm_mma_kernel<true><<<gemm_blocks, 256, gemm_smem>>>(bufB, W2, b2, bufH, n);
    aggregate_kernel<<<agg_blocks, 256>>>(bufH, bufB, n);
    // pool + head
    pool_head_kernel<<<G_, HD>>>(bufB, gidx, Wfc, bfc, Wout, bout,
                                 (float*)d_out, n);
}

// round 14
// speedup vs baseline: 1.0363x; 1.0363x over previous
#include <cuda_runtime.h>
#include <cuda_fp16.h>
#include <mma.h>
using namespace nvcuda;

#define HD 128
#define MAXN 100096
#define MAXE 1600000
#define SK 136   // smem stride in halves (padded)
#define CAP 128  // fixed CSR bucket capacity per node (max degree ~45 for this data)

// ---------------- device scratch (static, no allocation) ----------------
__device__ __align__(16) __half g_bufH[MAXN * HD];  // GEMM output (fp16, gathered by agg)
__device__ __align__(16) __half g_bufB[MAXN * HD];  // aggregation output (fp16 activations)
__device__ int g_cnt[MAXN];          // per-dst degree (atomic)
__device__ int g_csr[MAXN * CAP];    // fixed-stride buckets of src indices

// ---------------- single-pass CSR build ----------------
__global__ void build_csr_kernel(const int* __restrict__ adj, int E_) {
    int e = blockIdx.x * blockDim.x + threadIdx.x;
    if (e < E_) {
        int s = adj[e];
        int d = adj[E_ + e];
        int slot = atomicAdd(&g_cnt[d], 1);
        if (slot < CAP) g_csr[d * CAP + slot] = s;
    }
}

// ---------------- tensor-core GEMM (R6/R10 version, verbatim) ----------------
// C[r] = fp16( (A[r] @ W + b) * norm[r] ),  norm[r] = rsqrt(cnt[r]) (0 if cnt==0)
// 256 threads, 128-row tile, K=128 resident, HMMA fp16-in/fp32-accum.
template<bool AHALF>
__global__ void gemm_mma_kernel(const void* __restrict__ Ain,
                                const float* __restrict__ W,
                                const float* __restrict__ bias,
                                __half* __restrict__ C, int n) {
    extern __shared__ char smem_raw[];
    __half* As = (__half*)smem_raw;           // 128 x SK halves
    __half* Ws = As + 128 * SK;               // 128 x SK halves
    float* stage = (float*)smem_raw;          // reused after mma loop
    int tid = threadIdx.x;
    int row0 = blockIdx.x * 128;

    // W fp32 -> fp16 smem
    {
        const float4* W4 = (const float4*)W;
        #pragma unroll
        for (int i = tid; i < 128 * 32; i += 256) {
            int r = i >> 5, c4 = i & 31;
            float4 v = W4[i];
            __half2* d = (__half2*)(Ws + r * SK + c4 * 4);
            d[0] = __floats2half2_rn(v.x, v.y);
            d[1] = __floats2half2_rn(v.z, v.w);
        }
    }
    // A tile -> fp16 smem
    if (AHALF) {
        const uint4* A4 = (const uint4*)Ain;   // 8 halves per uint4, 16 per row
        #pragma unroll
        for (int i = tid; i < 128 * 16; i += 256) {
            int r = i >> 4, c8 = i & 15;
            int gr = row0 + r;
            uint4 v = (gr < n) ? A4[gr * 16 + c8] : make_uint4(0, 0, 0, 0);
            *(uint4*)(As + r * SK + c8 * 8) = v;
        }
    } else {
        const float4* A4 = (const float4*)Ain;
        #pragma unroll
        for (int i = tid; i < 128 * 32; i += 256) {
            int r = i >> 5, c4 = i & 31;
            int gr = row0 + r;
            float4 v = (gr < n) ? A4[gr * 32 + c4] : make_float4(0.f, 0.f, 0.f, 0.f);
            __half2* d = (__half2*)(As + r * SK + c4 * 4);
            d[0] = __floats2half2_rn(v.x, v.y);
            d[1] = __floats2half2_rn(v.z, v.w);
        }
    }
    __syncthreads();

    int w = tid >> 5;
    int lane = tid & 31;
    int wm = (w >> 1) * 32;     // warp row base
    int wn = (w & 1) * 64;      // warp col base

    wmma::fragment<wmma::accumulator, 16, 16, 16, float> acc[2][4];
    #pragma unroll
    for (int p = 0; p < 2; p++)
        #pragma unroll
        for (int q = 0; q < 4; q++) wmma::fill_fragment(acc[p][q], 0.0f);

    #pragma unroll
    for (int k = 0; k < 128; k += 16) {
        wmma::fragment<wmma::matrix_a, 16, 16, 16, __half, wmma::row_major> af[2];
        wmma::fragment<wmma::matrix_b, 16, 16, 16, __half, wmma::row_major> bf[4];
        #pragma unroll
        for (int p = 0; p < 2; p++)
            wmma::load_matrix_sync(af[p], As + (wm + 16 * p) * SK + k, SK);
        #pragma unroll
        for (int q = 0; q < 4; q++)
            wmma::load_matrix_sync(bf[q], Ws + k * SK + wn + 16 * q, SK);
        #pragma unroll
        for (int p = 0; p < 2; p++)
            #pragma unroll
            for (int q = 0; q < 4; q++)
                wmma::mma_sync(acc[p][q], af[p], bf[q], acc[p][q]);
    }
    __syncthreads();   // all warps done reading As/Ws before staging overwrites

    float* st = stage + w * (32 * 72);
    #pragma unroll
    for (int p = 0; p < 2; p++)
        #pragma unroll
        for (int q = 0; q < 4; q++)
            wmma::store_matrix_sync(st + 16 * p * 72 + 16 * q, acc[p][q], 72,
                                    wmma::mem_row_major);
    __syncwarp();

    // epilogue: (v + bias) * norm[row] -> fp16
    float2 bb = ((const float2*)bias)[(wn >> 1) + lane];
    __half2* C2 = (__half2*)C;
    #pragma unroll
    for (int r = 0; r < 32; r++) {
        int gr = row0 + wm + r;
        if (gr < n) {
            int c = g_cnt[gr];
            float nr = (c > 0) ? rsqrtf((float)c) : 0.0f;
            float2 v = *(float2*)(st + r * 72 + lane * 2);
            C2[gr * 64 + (wn >> 1) + lane] =
                __floats2half2_rn((v.x + bb.x) * nr, (v.y + bb.y) * nr);
        }
    }
}

// ---- aggregation (R12 verbatim): QUAD inner step, two-level fp16 pairwise adds ----
__global__ void aggregate_kernel(const __half* __restrict__ Hs,
                                 __half* __restrict__ Out, int n) {
    int gw = (blockIdx.x * blockDim.x + threadIdx.x) >> 5;
    int lane = threadIdx.x & 31;
    if (gw >= n) return;
    int cnt_true = g_cnt[gw];
    int cnt = cnt_true < CAP ? cnt_true : CAP;
    const int* bucket = g_csr + gw * CAP;
    const uint2* H2 = (const uint2*)Hs;   // row stride = 32 uint2 (256B)
    float ax = 0.f, ay = 0.f, az = 0.f, aw = 0.f;
    for (int base = 0; base < cnt; base += 32) {
        int rem = cnt - base;
        int e = 0;
        if (lane < rem) e = bucket[base + lane];
        int m = rem < 32 ? rem : 32;
        int j = 0;
        for (; j + 4 <= m; j += 4) {
            int s0 = __shfl_sync(0xffffffffu, e, j);
            int s1 = __shfl_sync(0xffffffffu, e, j + 1);
            int s2 = __shfl_sync(0xffffffffu, e, j + 2);
            int s3 = __shfl_sync(0xffffffffu, e, j + 3);
            uint2 v0 = __ldg(&H2[s0 * 32 + lane]);
            uint2 v1 = __ldg(&H2[s1 * 32 + lane]);
            uint2 v2 = __ldg(&H2[s2 * 32 + lane]);
            uint2 v3 = __ldg(&H2[s3 * 32 + lane]);
            __half2 p0 = __hadd2(*(__half2*)&v0.x, *(__half2*)&v1.x);
            __half2 p1 = __hadd2(*(__half2*)&v0.y, *(__half2*)&v1.y);
            __half2 q0 = __hadd2(*(__half2*)&v2.x, *(__half2*)&v3.x);
            __half2 q1 = __hadd2(*(__half2*)&v2.y, *(__half2*)&v3.y);
            __half2 r0 = __hadd2(p0, q0);
            __half2 r1 = __hadd2(p1, q1);
            float2 f0 = __half22float2(r0);
            float2 f1 = __half22float2(r1);
            ax += f0.x; ay += f0.y; az += f1.x; aw += f1.y;
        }
        if (j + 2 <= m) {
            int s0 = __shfl_sync(0xffffffffu, e, j);
            int s1 = __shfl_sync(0xffffffffu, e, j + 1);
            uint2 v0 = __ldg(&H2[s0 * 32 + lane]);
            uint2 v1 = __ldg(&H2[s1 * 32 + lane]);
            __half2 p0 = __hadd2(*(__half2*)&v0.x, *(__half2*)&v1.x);
            __half2 p1 = __hadd2(*(__half2*)&v0.y, *(__half2*)&v1.y);
            float2 f0 = __half22float2(p0);
            float2 f1 = __half22float2(p1);
            ax += f0.x; ay += f0.y; az += f1.x; aw += f1.y;
            j += 2;
        }
        if (j < m) {
            int s = __shfl_sync(0xffffffffu, e, j);
            uint2 v = __ldg(&H2[s * 32 + lane]);
            float2 f0 = __half22float2(*(__half2*)&v.x);
            float2 f1 = __half22float2(*(__half2*)&v.y);
            ax += f0.x; ay += f0.y; az += f1.x; aw += f1.y;
        }
    }
    float nr = (cnt_true > 0) ? rsqrtf((float)cnt_true) : 0.0f;
    __half2 o0 = __floats2half2_rn(fmaxf(ax * nr, 0.f), fmaxf(ay * nr, 0.f));
    __half2 o1 = __floats2half2_rn(fmaxf(az * nr, 0.f), fmaxf(aw * nr, 0.f));
    uint2 o;
    o.x = *(unsigned*)&o0;
    o.y = *(unsigned*)&o1;
    ((uint2*)Out)[gw * 32 + lane] = o;
}

// ---------------- pooling + MLP head (one block per graph, 256 threads) ----------------
__device__ __forceinline__ int lower_bound_dev(const int* a, int n, int key) {
    int lo = 0, hi = n;
    while (lo < hi) {
        int mid = (lo + hi) >> 1;
        if (a[mid] < key) lo = mid + 1; else hi = mid;
    }
    return lo;
}

__global__ void pool_head_kernel(const __half* __restrict__ H,
                                 const int* __restrict__ gidx,
                                 const float* __restrict__ Wfc,
                                 const float* __restrict__ bfc,
                                 const float* __restrict__ Wout,
                                 const float* __restrict__ bout,
                                 float* __restrict__ out, int n) {
    __shared__ float gf[HD];
    __shared__ float part[2][HD];
    __shared__ float red[HD];
    __shared__ int bounds[2];
    int t = threadIdx.x;
    int col = t & 127;
    int half = t >> 7;          // 0 or 1
    int g = blockIdx.x;
    if (t < 2) bounds[t] = lower_bound_dev(gidx, n, g + t);
    __syncthreads();
    int start = bounds[0], end = bounds[1];

    // pooling: row-interleaved split across the two halves (halves the serial chain)
    float s = 0.f;
    for (int i = start + half; i < end; i += 2)
        s += __half2float(H[i * HD + col]);
    part[half][col] = s;
    __syncthreads();
    if (half == 0)
        gf[col] = (part[0][col] + part[1][col]) /
                  fmaxf((float)(end - start), 1.0f);
    __syncthreads();

    // FC: k-range split across the two halves
    float acc = 0.f;
    int k0 = half * 64;
    #pragma unroll 8
    for (int k = k0; k < k0 + 64; k++) acc += gf[k] * Wfc[k * HD + col];
    part[half][col] = acc;
    __syncthreads();

    if (half == 0) {
        float a = part[0][col] + part[1][col] + bfc[col];
        red[col] = fmaxf(a, 0.f) * Wout[col];
    }
    __syncthreads();
    #pragma unroll
    for (int sft = 64; sft > 0; sft >>= 1) {
        if (t < sft) red[t] += red[t + sft];
        __syncthreads();
    }
    if (t == 0) out[g] = red[0] + bout[0];
}

// ---------------- launch ----------------
extern "C" void kernel_launch(void* const* d_in, const int* in_sizes, int n_in,
                              void* d_out, int out_size) {
    const float* node = (const float*)d_in[0];
    const int*   adj  = (const int*)d_in[1];
    const int*   gidx = (const int*)d_in[2];
    // d_in[3] = is_training (ignored, eval mode)
    const float* W1   = (const float*)d_in[4];
    const float* b1   = (const float*)d_in[5];
    const float* W2   = (const float*)d_in[6];
    const float* b2   = (const float*)d_in[7];
    const float* Wfc  = (const float*)d_in[8];
    const float* bfc  = (const float*)d_in[9];
    const float* Wout = (const float*)d_in[10];
    const float* bout = (const float*)d_in[11];

    int n  = in_sizes[2];          // N nodes
    int E_ = in_sizes[1] / 2;      // E edges
    int G_ = out_size;             // G graphs (OUT=1)

    __half* bufH; __half* bufB; int* cntPtr;
    cudaGetSymbolAddress((void**)&bufH, g_bufH);
    cudaGetSymbolAddress((void**)&bufB, g_bufB);
    cudaGetSymbolAddress((void**)&cntPtr, g_cnt);

    // smem: max(two 128xSK half tiles, 8 warps * 32*72 floats staging)
    const int gemm_smem = (2 * 128 * SK * 2 > 8 * 32 * 72 * 4)
                              ? 2 * 128 * SK * 2 : 8 * 32 * 72 * 4;
    cudaFuncSetAttribute(gemm_mma_kernel<false>,
                         cudaFuncAttributeMaxDynamicSharedMemorySize, gemm_smem);
    cudaFuncSetAttribute(gemm_mma_kernel<true>,
                         cudaFuncAttributeMaxDynamicSharedMemorySize, gemm_smem);

    int gemm_blocks = (n + 127) / 128;
    int agg_blocks  = (n + 7) / 8;   // 8 warps / block, 1 warp per node

    // single-pass CSR build (degrees + fixed-stride buckets)
    cudaMemsetAsync(cntPtr, 0, (size_t)MAXN * sizeof(int));
    build_csr_kernel<<<(E_ + 255) / 256, 256>>>(adj, E_);

    // layer 1
    gemm_mma_kernel<false><<<gemm_blocks, 256, gemm_smem>>>(node, W1, b1, bufH, n);
    aggregate_kernel<<<agg_blocks, 256>>>(bufH, bufB, n);
    // layer 2
    gemm_mma_kernel<true><<<gemm_blocks, 256, gemm_smem>>>(bufB, W2, b2, bufH, n);
    aggregate_kernel<<<agg_blocks, 256>>>(bufH, bufB, n);
    // pool + head
    pool_head_kernel<<<G_, 256>>>(bufB, gidx, Wfc, bfc, Wout, bout,
                                  (float*)d_out, n);
}

// round 15
// speedup vs baseline: 1.0807x; 1.0429x over previous
#include <cuda_runtime.h>
#include <cuda_fp16.h>
#include <mma.h>
using namespace nvcuda;

#define HD 128
#define MAXN 100096
#define MAXE 1600000
#define SK 136   // smem stride in halves (padded)
#define CAP 128  // fixed CSR bucket capacity per node (max degree ~45 for this data)

// ---------------- device scratch (static, no allocation) ----------------
__device__ __align__(16) __half g_bufH[MAXN * HD];  // GEMM output (fp16, gathered by agg)
__device__ __align__(16) __half g_bufB[MAXN * HD];  // aggregation output (fp16 activations)
__device__ int g_cnt[MAXN];          // per-dst degree (atomic)
__device__ int g_csr[MAXN * CAP];    // fixed-stride buckets of src indices

// ---------------- single-pass CSR build ----------------
__global__ void build_csr_kernel(const int* __restrict__ adj, int E_) {
    int e = blockIdx.x * blockDim.x + threadIdx.x;
    if (e < E_) {
        int s = adj[e];
        int d = adj[E_ + e];
        int slot = atomicAdd(&g_cnt[d], 1);
        if (slot < CAP) g_csr[d * CAP + slot] = s;
    }
}

// ---------------- tensor-core GEMM ----------------
// C[r] = fp16( (A[r] @ W + b) * norm[r] ),  norm[r] = rsqrt(cnt[r]) (0 if cnt==0)
// 256 threads, 128-row tile, K=128 resident, HMMA fp16-in/fp32-accum.
// __launch_bounds__(256, 2): RAISES the ptxas register budget 96 -> 128 while
// keeping the same 2 blocks/SM (smem-capped anyway), giving headroom to
// software-pipeline fragment loads across k-steps.
template<bool AHALF>
__global__ void __launch_bounds__(256, 2)
gemm_mma_kernel(const void* __restrict__ Ain,
                const float* __restrict__ W,
                const float* __restrict__ bias,
                __half* __restrict__ C, int n) {
    extern __shared__ char smem_raw[];
    __half* As = (__half*)smem_raw;           // 128 x SK halves
    __half* Ws = As + 128 * SK;               // 128 x SK halves
    float* stage = (float*)smem_raw;          // reused after mma loop
    int tid = threadIdx.x;
    int row0 = blockIdx.x * 128;

    // W fp32 -> fp16 smem
    {
        const float4* W4 = (const float4*)W;
        #pragma unroll
        for (int i = tid; i < 128 * 32; i += 256) {
            int r = i >> 5, c4 = i & 31;
            float4 v = W4[i];
            __half2* d = (__half2*)(Ws + r * SK + c4 * 4);
            d[0] = __floats2half2_rn(v.x, v.y);
            d[1] = __floats2half2_rn(v.z, v.w);
        }
    }
    // A tile -> fp16 smem
    if (AHALF) {
        const uint4* A4 = (const uint4*)Ain;   // 8 halves per uint4, 16 per row
        #pragma unroll
        for (int i = tid; i < 128 * 16; i += 256) {
            int r = i >> 4, c8 = i & 15;
            int gr = row0 + r;
            uint4 v = (gr < n) ? A4[gr * 16 + c8] : make_uint4(0, 0, 0, 0);
            *(uint4*)(As + r * SK + c8 * 8) = v;
        }
    } else {
        const float4* A4 = (const float4*)Ain;
        #pragma unroll
        for (int i = tid; i < 128 * 32; i += 256) {
            int r = i >> 5, c4 = i & 31;
            int gr = row0 + r;
            float4 v = (gr < n) ? A4[gr * 32 + c4] : make_float4(0.f, 0.f, 0.f, 0.f);
            __half2* d = (__half2*)(As + r * SK + c4 * 4);
            d[0] = __floats2half2_rn(v.x, v.y);
            d[1] = __floats2half2_rn(v.z, v.w);
        }
    }
    __syncthreads();

    int w = tid >> 5;
    int lane = tid & 31;
    int wm = (w >> 1) * 32;     // warp row base
    int wn = (w & 1) * 64;      // warp col base

    wmma::fragment<wmma::accumulator, 16, 16, 16, float> acc[2][4];
    #pragma unroll
    for (int p = 0; p < 2; p++)
        #pragma unroll
        for (int q = 0; q < 4; q++) wmma::fill_fragment(acc[p][q], 0.0f);

    #pragma unroll
    for (int k = 0; k < 128; k += 16) {
        wmma::fragment<wmma::matrix_a, 16, 16, 16, __half, wmma::row_major> af[2];
        wmma::fragment<wmma::matrix_b, 16, 16, 16, __half, wmma::row_major> bf[4];
        #pragma unroll
        for (int p = 0; p < 2; p++)
            wmma::load_matrix_sync(af[p], As + (wm + 16 * p) * SK + k, SK);
        #pragma unroll
        for (int q = 0; q < 4; q++)
            wmma::load_matrix_sync(bf[q], Ws + k * SK + wn + 16 * q, SK);
        #pragma unroll
        for (int p = 0; p < 2; p++)
            #pragma unroll
            for (int q = 0; q < 4; q++)
                wmma::mma_sync(acc[p][q], af[p], bf[q], acc[p][q]);
    }
    __syncthreads();   // all warps done reading As/Ws before staging overwrites

    float* st = stage + w * (32 * 72);
    #pragma unroll
    for (int p = 0; p < 2; p++)
        #pragma unroll
        for (int q = 0; q < 4; q++)
            wmma::store_matrix_sync(st + 16 * p * 72 + 16 * q, acc[p][q], 72,
                                    wmma::mem_row_major);
    __syncwarp();

    // epilogue: (v + bias) * norm[row] -> fp16
    float2 bb = ((const float2*)bias)[(wn >> 1) + lane];
    __half2* C2 = (__half2*)C;
    #pragma unroll
    for (int r = 0; r < 32; r++) {
        int gr = row0 + wm + r;
        if (gr < n) {
            int c = g_cnt[gr];
            float nr = (c > 0) ? rsqrtf((float)c) : 0.0f;
            float2 v = *(float2*)(st + r * 72 + lane * 2);
            C2[gr * 64 + (wn >> 1) + lane] =
                __floats2half2_rn((v.x + bb.x) * nr, (v.y + bb.y) * nr);
        }
    }
}

// ---- aggregation (R12 verbatim): QUAD inner step, two-level fp16 pairwise adds ----
__global__ void aggregate_kernel(const __half* __restrict__ Hs,
                                 __half* __restrict__ Out, int n) {
    int gw = (blockIdx.x * blockDim.x + threadIdx.x) >> 5;
    int lane = threadIdx.x & 31;
    if (gw >= n) return;
    int cnt_true = g_cnt[gw];
    int cnt = cnt_true < CAP ? cnt_true : CAP;
    const int* bucket = g_csr + gw * CAP;
    const uint2* H2 = (const uint2*)Hs;   // row stride = 32 uint2 (256B)
    float ax = 0.f, ay = 0.f, az = 0.f, aw = 0.f;
    for (int base = 0; base < cnt; base += 32) {
        int rem = cnt - base;
        int e = 0;
        if (lane < rem) e = bucket[base + lane];
        int m = rem < 32 ? rem : 32;
        int j = 0;
        for (; j + 4 <= m; j += 4) {
            int s0 = __shfl_sync(0xffffffffu, e, j);
            int s1 = __shfl_sync(0xffffffffu, e, j + 1);
            int s2 = __shfl_sync(0xffffffffu, e, j + 2);
            int s3 = __shfl_sync(0xffffffffu, e, j + 3);
            uint2 v0 = __ldg(&H2[s0 * 32 + lane]);
            uint2 v1 = __ldg(&H2[s1 * 32 + lane]);
            uint2 v2 = __ldg(&H2[s2 * 32 + lane]);
            uint2 v3 = __ldg(&H2[s3 * 32 + lane]);
            __half2 p0 = __hadd2(*(__half2*)&v0.x, *(__half2*)&v1.x);
            __half2 p1 = __hadd2(*(__half2*)&v0.y, *(__half2*)&v1.y);
            __half2 q0 = __hadd2(*(__half2*)&v2.x, *(__half2*)&v3.x);
            __half2 q1 = __hadd2(*(__half2*)&v2.y, *(__half2*)&v3.y);
            __half2 r0 = __hadd2(p0, q0);
            __half2 r1 = __hadd2(p1, q1);
            float2 f0 = __half22float2(r0);
            float2 f1 = __half22float2(r1);
            ax += f0.x; ay += f0.y; az += f1.x; aw += f1.y;
        }
        if (j + 2 <= m) {
            int s0 = __shfl_sync(0xffffffffu, e, j);
            int s1 = __shfl_sync(0xffffffffu, e, j + 1);
            uint2 v0 = __ldg(&H2[s0 * 32 + lane]);
            uint2 v1 = __ldg(&H2[s1 * 32 + lane]);
            __half2 p0 = __hadd2(*(__half2*)&v0.x, *(__half2*)&v1.x);
            __half2 p1 = __hadd2(*(__half2*)&v0.y, *(__half2*)&v1.y);
            float2 f0 = __half22float2(p0);
            float2 f1 = __half22float2(p1);
            ax += f0.x; ay += f0.y; az += f1.x; aw += f1.y;
            j += 2;
        }
        if (j < m) {
            int s = __shfl_sync(0xffffffffu, e, j);
            uint2 v = __ldg(&H2[s * 32 + lane]);
            float2 f0 = __half22float2(*(__half2*)&v.x);
            float2 f1 = __half22float2(*(__half2*)&v.y);
            ax += f0.x; ay += f0.y; az += f1.x; aw += f1.y;
        }
    }
    float nr = (cnt_true > 0) ? rsqrtf((float)cnt_true) : 0.0f;
    __half2 o0 = __floats2half2_rn(fmaxf(ax * nr, 0.f), fmaxf(ay * nr, 0.f));
    __half2 o1 = __floats2half2_rn(fmaxf(az * nr, 0.f), fmaxf(aw * nr, 0.f));
    uint2 o;
    o.x = *(unsigned*)&o0;
    o.y = *(unsigned*)&o1;
    ((uint2*)Out)[gw * 32 + lane] = o;
}

// ---------------- pooling + MLP head (one block per graph, 256 threads) ----------------
__device__ __forceinline__ int lower_bound_dev(const int* a, int n, int key) {
    int lo = 0, hi = n;
    while (lo < hi) {
        int mid = (lo + hi) >> 1;
        if (a[mid] < key) lo = mid + 1; else hi = mid;
    }
    return lo;
}

__global__ void pool_head_kernel(const __half* __restrict__ H,
                                 const int* __restrict__ gidx,
                                 const float* __restrict__ Wfc,
                                 const float* __restrict__ bfc,
                                 const float* __restrict__ Wout,
                                 const float* __restrict__ bout,
                                 float* __restrict__ out, int n) {
    __shared__ float gf[HD];
    __shared__ float part[2][HD];
    __shared__ float red[HD];
    __shared__ int bounds[2];
    int t = threadIdx.x;
    int col = t & 127;
    int half = t >> 7;          // 0 or 1
    int g = blockIdx.x;
    if (t < 2) bounds[t] = lower_bound_dev(gidx, n, g + t);
    __syncthreads();
    int start = bounds[0], end = bounds[1];

    // pooling: row-interleaved split across the two halves (halves the serial chain)
    float s = 0.f;
    for (int i = start + half; i < end; i += 2)
        s += __half2float(H[i * HD + col]);
    part[half][col] = s;
    __syncthreads();
    if (half == 0)
        gf[col] = (part[0][col] + part[1][col]) /
                  fmaxf((float)(end - start), 1.0f);
    __syncthreads();

    // FC: k-range split across the two halves
    float acc = 0.f;
    int k0 = half * 64;
    #pragma unroll 8
    for (int k = k0; k < k0 + 64; k++) acc += gf[k] * Wfc[k * HD + col];
    part[half][col] = acc;
    __syncthreads();

    if (half == 0) {
        float a = part[0][col] + part[1][col] + bfc[col];
        red[col] = fmaxf(a, 0.f) * Wout[col];
    }
    __syncthreads();
    #pragma unroll
    for (int sft = 64; sft > 0; sft >>= 1) {
        if (t < sft) red[t] += red[t + sft];
        __syncthreads();
    }
    if (t == 0) out[g] = red[0] + bout[0];
}

// ---------------- launch ----------------
extern "C" void kernel_launch(void* const* d_in, const int* in_sizes, int n_in,
                              void* d_out, int out_size) {
    const float* node = (const float*)d_in[0];
    const int*   adj  = (const int*)d_in[1];
    const int*   gidx = (const int*)d_in[2];
    // d_in[3] = is_training (ignored, eval mode)
    const float* W1   = (const float*)d_in[4];
    const float* b1   = (const float*)d_in[5];
    const float* W2   = (const float*)d_in[6];
    const float* b2   = (const float*)d_in[7];
    const float* Wfc  = (const float*)d_in[8];
    const float* bfc  = (const float*)d_in[9];
    const float* Wout = (const float*)d_in[10];
    const float* bout = (const float*)d_in[11];

    int n  = in_sizes[2];          // N nodes
    int E_ = in_sizes[1] / 2;      // E edges
    int G_ = out_size;             // G graphs (OUT=1)

    __half* bufH; __half* bufB; int* cntPtr;
    cudaGetSymbolAddress((void**)&bufH, g_bufH);
    cudaGetSymbolAddress((void**)&bufB, g_bufB);
    cudaGetSymbolAddress((void**)&cntPtr, g_cnt);

    // smem: max(two 128xSK half tiles, 8 warps * 32*72 floats staging)
    const int gemm_smem = (2 * 128 * SK * 2 > 8 * 32 * 72 * 4)
                              ? 2 * 128 * SK * 2 : 8 * 32 * 72 * 4;
    cudaFuncSetAttribute(gemm_mma_kernel<false>,
                         cudaFuncAttributeMaxDynamicSharedMemorySize, gemm_smem);
    cudaFuncSetAttribute(gemm_mma_kernel<true>,
                         cudaFuncAttributeMaxDynamicSharedMemorySize, gemm_smem);

    int gemm_blocks = (n + 127) / 128;
    int agg_blocks  = (n + 7) / 8;   // 8 warps / block, 1 warp per node

    // single-pass CSR build (degrees + fixed-stride buckets)
    cudaMemsetAsync(cntPtr, 0, (size_t)MAXN * sizeof(int));
    build_csr_kernel<<<(E_ + 255) / 256, 256>>>(adj, E_);

    // layer 1
    gemm_mma_kernel<false><<<gemm_blocks, 256, gemm_smem>>>(node, W1, b1, bufH, n);
    aggregate_kernel<<<agg_blocks, 256>>>(bufH, bufB, n);
    // layer 2
    gemm_mma_kernel<true><<<gemm_blocks, 256, gemm_smem>>>(bufB, W2, b2, bufH, n);
    aggregate_kernel<<<agg_blocks, 256>>>(bufH, bufB, n);
    // pool + head
    pool_head_kernel<<<G_, 256>>>(bufB, gidx, Wfc, bfc, Wout, bout,
                                  (float*)d_out, n);
}